// round 2
// baseline (speedup 1.0000x reference)
#include <cuda_runtime.h>
#include <cuda_bf16.h>
#include <cstdint>

// DistMult decoder: out[e] = sigmoid( sum_d x[l,d] * R[t,d] * x[r,d] )
// E = 4,000,000 edges, D = 32 (one row = 128B = one L2 line).
// x table = 12.8MB -> resides in L2. Bottleneck = L2 gather bandwidth.
//
// Indices are int32 (JAX x64 disabled -> jnp.int64 request degrades to int32).
//
// One thread per edge. float4 loads give 8 LDG.128 per gathered row,
// high MLP, in-register reduction. edge_type is sorted, so R-row loads
// are effectively broadcast across adjacent threads (L1 hits).

#define DIM 32

__global__ void __launch_bounds__(256) distmult_kernel(
    const float* __restrict__ x,
    const float* __restrict__ R,
    const int* __restrict__ edge_index,  // [2, E] int32
    const int* __restrict__ edge_type,   // [E] int32
    float* __restrict__ out,
    int E)
{
    int e = blockIdx.x * blockDim.x + threadIdx.x;
    if (e >= E) return;

    int l = edge_index[e];
    int r = edge_index[E + e];
    int t = edge_type[e];

    const float4* __restrict__ xl = reinterpret_cast<const float4*>(x + (size_t)l * DIM);
    const float4* __restrict__ xr = reinterpret_cast<const float4*>(x + (size_t)r * DIM);
    const float4* __restrict__ rv = reinterpret_cast<const float4*>(R + (size_t)t * DIM);

    float s = 0.0f;
#pragma unroll
    for (int i = 0; i < DIM / 4; i++) {
        float4 a = xl[i];
        float4 b = xr[i];
        float4 c = rv[i];
        s = fmaf(a.x * c.x, b.x, s);
        s = fmaf(a.y * c.y, b.y, s);
        s = fmaf(a.z * c.z, b.z, s);
        s = fmaf(a.w * c.w, b.w, s);
    }

    // sigmoid; __expf precision ~2 ulp, far below the 1e-3 rel-err gate
    out[e] = 1.0f / (1.0f + __expf(-s));
}

extern "C" void kernel_launch(void* const* d_in, const int* in_sizes, int n_in,
                              void* d_out, int out_size)
{
    const float* x  = (const float*)d_in[0];   // [N_NODES, 32]
    const float* R  = (const float*)d_in[1];   // [N_REL, 32]
    const int*   ei = (const int*)d_in[2];     // [2, E] int32
    const int*   et = (const int*)d_in[3];     // [E] int32
    float* out = (float*)d_out;

    int E = in_sizes[3];  // element count of edge_type == number of edges

    const int threads = 256;
    int blocks = (E + threads - 1) / threads;
    distmult_kernel<<<blocks, threads>>>(x, R, ei, et, out, E);
}

// round 3
// speedup vs baseline: 2.1289x; 2.1289x over previous
#include <cuda_runtime.h>
#include <cuda_bf16.h>
#include <cstdint>

// DistMult decoder: out[e] = sigmoid( sum_d x[l,d] * R[t,d] * x[r,d] )
// E = 4M edges, D = 32 floats (one row = 128B = one L2 line).
//
// R2 finding: one-thread-per-edge saturates L1tex (96%) because each warp-wide
// LDG.128 touches up to 32 distinct lines (32 wavefronts). Fix: 8 lanes per
// edge, lane i loads float4 at row offset i*16B -> each edge row is ONE
// coalesced 128B line; a warp's LDG.128 touches only 4 lines (4 edges/warp).
// 8x fewer L1 wavefronts; L2 gather bandwidth becomes the ceiling.

#define DIM 32

__global__ void __launch_bounds__(256) distmult_kernel(
    const float* __restrict__ x,
    const float* __restrict__ R,
    const int* __restrict__ edge_index,  // [2, E] int32
    const int* __restrict__ edge_type,   // [E] int32
    float* __restrict__ out,
    int E)
{
    int tid = blockIdx.x * blockDim.x + threadIdx.x;
    int e = tid >> 3;           // 8 lanes per edge
    int i = threadIdx.x & 7;    // lane's chunk within the row (i*4 floats)
    if (e >= E) return;

    // All 8 lanes of a group read the same index words (same sector -> broadcast)
    int l = edge_index[e];
    int r = edge_index[E + e];
    int t = edge_type[e];

    float4 a = *reinterpret_cast<const float4*>(x + (size_t)l * DIM + i * 4);
    float4 b = *reinterpret_cast<const float4*>(x + (size_t)r * DIM + i * 4);
    float4 c = *reinterpret_cast<const float4*>(R + (size_t)t * DIM + i * 4);

    float s;
    s = a.x * c.x * b.x;
    s = fmaf(a.y * c.y, b.y, s);
    s = fmaf(a.z * c.z, b.z, s);
    s = fmaf(a.w * c.w, b.w, s);

    // reduce across the 8-lane group
    s += __shfl_xor_sync(0xFFFFFFFFu, s, 1);
    s += __shfl_xor_sync(0xFFFFFFFFu, s, 2);
    s += __shfl_xor_sync(0xFFFFFFFFu, s, 4);

    if (i == 0) {
        // lanes 0,8,16,24 write 4 consecutive floats -> one 16B sector per warp
        out[e] = 1.0f / (1.0f + __expf(-s));
    }
}

extern "C" void kernel_launch(void* const* d_in, const int* in_sizes, int n_in,
                              void* d_out, int out_size)
{
    const float* x  = (const float*)d_in[0];   // [N_NODES, 32]
    const float* R  = (const float*)d_in[1];   // [N_REL, 32]
    const int*   ei = (const int*)d_in[2];     // [2, E] int32
    const int*   et = (const int*)d_in[3];     // [E] int32
    float* out = (float*)d_out;

    int E = in_sizes[3];

    const int threads = 256;
    long long total = (long long)E * 8;
    int blocks = (int)((total + threads - 1) / threads);
    distmult_kernel<<<blocks, threads>>>(x, R, ei, et, out, E);
}

// round 4
// speedup vs baseline: 2.7636x; 1.2981x over previous
#include <cuda_runtime.h>
#include <cuda_bf16.h>
#include <cstdint>

// DistMult decoder: out[e] = sigmoid( sum_d x[l,d] * R[t,d] * x[r,d] )
// E = 4M edges, D = 32 floats (row = 128B = one L2 line).
//
// R3 finding: 8-lanes-per-edge removed the L1 wavefront bottleneck, but
// nothing is saturated (L1 48%, L2 32%, issue 40%) -> latency-bound with
// MLP=3 per thread. Fix: each 8-lane group processes 4 edges -> 12
// independent LDG.128 per thread + int4 index loads. Packed butterfly
// reduction: 7 SHFLs per 4 edges.

#define DIM 32

__global__ void __launch_bounds__(256) distmult_kernel(
    const float* __restrict__ x,
    const float* __restrict__ R,
    const int* __restrict__ edge_index,  // [2, E] int32
    const int* __restrict__ edge_type,   // [E] int32
    float* __restrict__ out,
    int E)
{
    int tid = blockIdx.x * blockDim.x + threadIdx.x;
    int g = tid >> 3;           // 8-lane group id; group handles edges 4g..4g+3
    int i = threadIdx.x & 7;    // lane's 16B chunk within a row
    int e0 = g * 4;
    if (e0 >= E) return;

    const float4* __restrict__ xv = reinterpret_cast<const float4*>(x);
    const float4* __restrict__ rv = reinterpret_cast<const float4*>(R);

    if (e0 + 3 < E) {
        // vector index loads (E % 4 == 0 in this dataset; guarded by branch)
        int4 L = reinterpret_cast<const int4*>(edge_index)[g];
        int4 Rt = reinterpret_cast<const int4*>(edge_index + E)[g];
        int4 T = reinterpret_cast<const int4*>(edge_type)[g];

        // 12 independent 16B gathers, all coalesced per 8-lane group
        float4 a0 = xv[(size_t)L.x * 8 + i];
        float4 a1 = xv[(size_t)L.y * 8 + i];
        float4 a2 = xv[(size_t)L.z * 8 + i];
        float4 a3 = xv[(size_t)L.w * 8 + i];
        float4 b0 = xv[(size_t)Rt.x * 8 + i];
        float4 b1 = xv[(size_t)Rt.y * 8 + i];
        float4 b2 = xv[(size_t)Rt.z * 8 + i];
        float4 b3 = xv[(size_t)Rt.w * 8 + i];
        float4 c0 = rv[(size_t)T.x * 8 + i];
        float4 c1 = rv[(size_t)T.y * 8 + i];
        float4 c2 = rv[(size_t)T.z * 8 + i];
        float4 c3 = rv[(size_t)T.w * 8 + i];

        float s0 = a0.x * c0.x * b0.x;
        s0 = fmaf(a0.y * c0.y, b0.y, s0);
        s0 = fmaf(a0.z * c0.z, b0.z, s0);
        s0 = fmaf(a0.w * c0.w, b0.w, s0);
        float s1 = a1.x * c1.x * b1.x;
        s1 = fmaf(a1.y * c1.y, b1.y, s1);
        s1 = fmaf(a1.z * c1.z, b1.z, s1);
        s1 = fmaf(a1.w * c1.w, b1.w, s1);
        float s2 = a2.x * c2.x * b2.x;
        s2 = fmaf(a2.y * c2.y, b2.y, s2);
        s2 = fmaf(a2.z * c2.z, b2.z, s2);
        s2 = fmaf(a2.w * c2.w, b2.w, s2);
        float s3 = a3.x * c3.x * b3.x;
        s3 = fmaf(a3.y * c3.y, b3.y, s3);
        s3 = fmaf(a3.z * c3.z, b3.z, s3);
        s3 = fmaf(a3.w * c3.w, b3.w, s3);

        // ---- packed 8-lane reduction of 4 values: 7 SHFLs ----
        // step 1: fold upper/lower halves of the 8-lane group
        s0 += __shfl_xor_sync(0xFFFFFFFFu, s0, 4);
        s1 += __shfl_xor_sync(0xFFFFFFFFu, s1, 4);
        s2 += __shfl_xor_sync(0xFFFFFFFFu, s2, 4);
        s3 += __shfl_xor_sync(0xFFFFFFFFu, s3, 4);
        // step 2: pair (s0,s1) and (s2,s3) across xor-2
        bool b2sel = (i & 2) != 0;
        float keep01 = b2sel ? s1 : s0;
        float send01 = b2sel ? s0 : s1;
        keep01 += __shfl_xor_sync(0xFFFFFFFFu, send01, 2);
        float keep23 = b2sel ? s3 : s2;
        float send23 = b2sel ? s2 : s3;
        keep23 += __shfl_xor_sync(0xFFFFFFFFu, send23, 2);
        // step 3: pair (keep01, keep23) across xor-1
        bool b1sel = (i & 1) != 0;
        float keep = b1sel ? keep23 : keep01;
        float send = b1sel ? keep01 : keep23;
        keep += __shfl_xor_sync(0xFFFFFFFFu, send, 1);
        // lane i (0..3) now holds edge e0 + ((i&1)<<1 | (i>>1)&1): 0,2,1,3

        if (i < 4) {
            int j = ((i & 1) << 1) | ((i >> 1) & 1);
            out[e0 + j] = 1.0f / (1.0f + __expf(-keep));
        }
    } else {
        // scalar tail (unused when E % 4 == 0, kept for safety)
        for (int e = e0; e < E; e++) {
            int l = edge_index[e];
            int r = edge_index[E + e];
            int t = edge_type[e];
            float4 a = xv[(size_t)l * 8 + i];
            float4 b = xv[(size_t)r * 8 + i];
            float4 c = rv[(size_t)t * 8 + i];
            float s = a.x * c.x * b.x;
            s = fmaf(a.y * c.y, b.y, s);
            s = fmaf(a.z * c.z, b.z, s);
            s = fmaf(a.w * c.w, b.w, s);
            s += __shfl_xor_sync(0xFFFFFFFFu, s, 1);
            s += __shfl_xor_sync(0xFFFFFFFFu, s, 2);
            s += __shfl_xor_sync(0xFFFFFFFFu, s, 4);
            if (i == 0) out[e] = 1.0f / (1.0f + __expf(-s));
        }
    }
}

extern "C" void kernel_launch(void* const* d_in, const int* in_sizes, int n_in,
                              void* d_out, int out_size)
{
    const float* x  = (const float*)d_in[0];   // [N_NODES, 32]
    const float* R  = (const float*)d_in[1];   // [N_REL, 32]
    const int*   ei = (const int*)d_in[2];     // [2, E] int32
    const int*   et = (const int*)d_in[3];     // [E] int32
    float* out = (float*)d_out;

    int E = in_sizes[3];

    const int threads = 256;
    long long groups = ((long long)E + 3) / 4;        // 4 edges per 8-lane group
    long long total = groups * 8;                      // threads needed
    int blocks = (int)((total + threads - 1) / threads);
    distmult_kernel<<<blocks, threads>>>(x, R, ei, et, out, E);
}

// round 5
// speedup vs baseline: 3.4491x; 1.2481x over previous
#include <cuda_runtime.h>
#include <cuda_bf16.h>
#include <cstdint>

// DistMult decoder: out[e] = sigmoid( sum_d x[l,d] * R[t,d] * x[r,d] )
// E = 4M edges, D = 32 floats (row = 128B = one L2 line).
//
// R4 analysis: ~5400 B/cyc of L2 gather traffic = ~85% of the measured LTS
// practical cap (6300 B/cyc). Remaining levers: occupancy (reg-capped) and
// in-flight bytes. edge_type is SORTED -> within a 4-edge group all types are
// equal except at ~964 boundaries: share one R row in the common path
// (saves 12 registers + 3 loads). launch_bounds(256,5) -> 40 warps/SM.

#define DIM 32

__global__ void __launch_bounds__(256, 5) distmult_kernel(
    const float* __restrict__ x,
    const float* __restrict__ R,
    const int* __restrict__ edge_index,  // [2, E] int32
    const int* __restrict__ edge_type,   // [E] int32
    float* __restrict__ out,
    int E)
{
    int tid = blockIdx.x * blockDim.x + threadIdx.x;
    int g = tid >> 3;           // 8-lane group; handles edges 4g..4g+3
    int i = threadIdx.x & 7;    // 16B chunk within a row
    int e0 = g * 4;
    if (e0 >= E) return;

    const float4* __restrict__ xv = reinterpret_cast<const float4*>(x);
    const float4* __restrict__ rv = reinterpret_cast<const float4*>(R);

    if (e0 + 3 < E) {
        int4 L  = reinterpret_cast<const int4*>(edge_index)[g];
        int4 Rt = reinterpret_cast<const int4*>(edge_index + E)[g];
        int4 T  = reinterpret_cast<const int4*>(edge_type)[g];

        // 8 independent coalesced 16B gathers (one 128B line per edge row)
        float4 a0 = xv[(size_t)L.x * 8 + i];
        float4 a1 = xv[(size_t)L.y * 8 + i];
        float4 a2 = xv[(size_t)L.z * 8 + i];
        float4 a3 = xv[(size_t)L.w * 8 + i];
        float4 b0 = xv[(size_t)Rt.x * 8 + i];
        float4 b1 = xv[(size_t)Rt.y * 8 + i];
        float4 b2 = xv[(size_t)Rt.z * 8 + i];
        float4 b3 = xv[(size_t)Rt.w * 8 + i];

        float s0, s1, s2, s3;
        if (T.x == T.w) {
            // common path (sorted types; ~99.9% of groups): one shared R row
            float4 c = rv[(size_t)T.x * 8 + i];
            s0 = a0.x * c.x * b0.x;
            s0 = fmaf(a0.y * c.y, b0.y, s0);
            s0 = fmaf(a0.z * c.z, b0.z, s0);
            s0 = fmaf(a0.w * c.w, b0.w, s0);
            s1 = a1.x * c.x * b1.x;
            s1 = fmaf(a1.y * c.y, b1.y, s1);
            s1 = fmaf(a1.z * c.z, b1.z, s1);
            s1 = fmaf(a1.w * c.w, b1.w, s1);
            s2 = a2.x * c.x * b2.x;
            s2 = fmaf(a2.y * c.y, b2.y, s2);
            s2 = fmaf(a2.z * c.z, b2.z, s2);
            s2 = fmaf(a2.w * c.w, b2.w, s2);
            s3 = a3.x * c.x * b3.x;
            s3 = fmaf(a3.y * c.y, b3.y, s3);
            s3 = fmaf(a3.z * c.z, b3.z, s3);
            s3 = fmaf(a3.w * c.w, b3.w, s3);
        } else {
            // relation boundary inside the group (rare)
            float4 c0 = rv[(size_t)T.x * 8 + i];
            float4 c1 = rv[(size_t)T.y * 8 + i];
            float4 c2 = rv[(size_t)T.z * 8 + i];
            float4 c3 = rv[(size_t)T.w * 8 + i];
            s0 = a0.x * c0.x * b0.x;
            s0 = fmaf(a0.y * c0.y, b0.y, s0);
            s0 = fmaf(a0.z * c0.z, b0.z, s0);
            s0 = fmaf(a0.w * c0.w, b0.w, s0);
            s1 = a1.x * c1.x * b1.x;
            s1 = fmaf(a1.y * c1.y, b1.y, s1);
            s1 = fmaf(a1.z * c1.z, b1.z, s1);
            s1 = fmaf(a1.w * c1.w, b1.w, s1);
            s2 = a2.x * c2.x * b2.x;
            s2 = fmaf(a2.y * c2.y, b2.y, s2);
            s2 = fmaf(a2.z * c2.z, b2.z, s2);
            s2 = fmaf(a2.w * c2.w, b2.w, s2);
            s3 = a3.x * c3.x * b3.x;
            s3 = fmaf(a3.y * c3.y, b3.y, s3);
            s3 = fmaf(a3.z * c3.z, b3.z, s3);
            s3 = fmaf(a3.w * c3.w, b3.w, s3);
        }

        // packed 8-lane reduction of 4 values: 7 SHFLs total
        s0 += __shfl_xor_sync(0xFFFFFFFFu, s0, 4);
        s1 += __shfl_xor_sync(0xFFFFFFFFu, s1, 4);
        s2 += __shfl_xor_sync(0xFFFFFFFFu, s2, 4);
        s3 += __shfl_xor_sync(0xFFFFFFFFu, s3, 4);
        bool b2sel = (i & 2) != 0;
        float keep01 = b2sel ? s1 : s0;
        float send01 = b2sel ? s0 : s1;
        keep01 += __shfl_xor_sync(0xFFFFFFFFu, send01, 2);
        float keep23 = b2sel ? s3 : s2;
        float send23 = b2sel ? s2 : s3;
        keep23 += __shfl_xor_sync(0xFFFFFFFFu, send23, 2);
        bool b1sel = (i & 1) != 0;
        float keep = b1sel ? keep23 : keep01;
        float send = b1sel ? keep01 : keep23;
        keep += __shfl_xor_sync(0xFFFFFFFFu, send, 1);
        // lane i in 0..3 holds edge e0 + ((i&1)<<1 | (i>>1))

        if (i < 4) {
            int j = ((i & 1) << 1) | ((i >> 1) & 1);
            out[e0 + j] = 1.0f / (1.0f + __expf(-keep));
        }
    } else {
        // scalar tail (unused when E % 4 == 0, kept for safety)
        for (int e = e0; e < E; e++) {
            int l = edge_index[e];
            int r = edge_index[E + e];
            int t = edge_type[e];
            float4 a = xv[(size_t)l * 8 + i];
            float4 b = xv[(size_t)r * 8 + i];
            float4 c = rv[(size_t)t * 8 + i];
            float s = a.x * c.x * b.x;
            s = fmaf(a.y * c.y, b.y, s);
            s = fmaf(a.z * c.z, b.z, s);
            s = fmaf(a.w * c.w, b.w, s);
            s += __shfl_xor_sync(0xFFFFFFFFu, s, 1);
            s += __shfl_xor_sync(0xFFFFFFFFu, s, 2);
            s += __shfl_xor_sync(0xFFFFFFFFu, s, 4);
            if (i == 0) out[e] = 1.0f / (1.0f + __expf(-s));
        }
    }
}

extern "C" void kernel_launch(void* const* d_in, const int* in_sizes, int n_in,
                              void* d_out, int out_size)
{
    const float* x  = (const float*)d_in[0];   // [N_NODES, 32]
    const float* R  = (const float*)d_in[1];   // [N_REL, 32]
    const int*   ei = (const int*)d_in[2];     // [2, E] int32
    const int*   et = (const int*)d_in[3];     // [E] int32
    float* out = (float*)d_out;

    int E = in_sizes[3];

    const int threads = 256;
    long long groups = ((long long)E + 3) / 4;
    long long total = groups * 8;
    int blocks = (int)((total + threads - 1) / threads);
    distmult_kernel<<<blocks, threads>>>(x, R, ei, et, out, E);
}